// round 1
// baseline (speedup 1.0000x reference)
#include <cuda_runtime.h>

// Problem constants
#define BB 4
#define XX 32
#define HH 8
#define WW 128
#define CC 32
#define NQ 128          // distinct query rows per batch = C*4
#define MM 4096         // key rows per batch = C*X*4
#define DD 256          // reduction dim = 32*8

// Scratch (device globals; allocation is forbidden)
__device__ float g_Q[BB*NQ*DD];      // [b][n][cc]
__device__ float g_K[BB*MM*DD];      // [b][m][cc]
__device__ float g_V[BB*MM*DD];      // [b][m][cc]
__device__ float g_S[BB*NQ*MM];      // scores -> probs
__device__ float g_O[BB*NQ*DD];      // attention output (pre-scatter)

// ---------------------------------------------------------------------------
// Kernel 1: Q projection.  Q[b, n=o*4+whi, cc=wlo*8+h] =
//   b_q[o] + sum_c w_q[o,c] * target[b,0,h, whi*32+wlo, c]
// ---------------------------------------------------------------------------
__global__ __launch_bounds__(256) void k_q(const float* __restrict__ target,
                                           const float* __restrict__ w_q,
                                           const float* __restrict__ b_q) {
    int t = blockIdx.x * 256 + threadIdx.x;       // [0, B*128*256)
    int b   = t >> 15;
    int n   = (t >> 8) & 127;
    int cc  = t & 255;
    int o   = n >> 2, whi = n & 3;
    int wlo = cc >> 3, h = cc & 7;
    int w   = whi * 32 + wlo;
    const float4* trow = (const float4*)(target + ((b*HH + h)*WW + w)*CC);
    const float4* wrow = (const float4*)(w_q + o*CC);
    float acc = b_q[o];
#pragma unroll
    for (int i = 0; i < 8; i++) {
        float4 a = trow[i], ww = wrow[i];
        acc += a.x*ww.x + a.y*ww.y + a.z*ww.z + a.w*ww.w;
    }
    g_Q[t] = acc;
}

// ---------------------------------------------------------------------------
// Kernel 2: conv3d (3,1,1) over X producing K and V in attention layout.
// out[b,o,x,w,h] = b_cross[o] + sum_{ci,dx} w_cross[o,ci,dx]*storage[b,x+dx-1,h,w,ci]
// o<32 -> V channel o ; o>=32 -> K channel o-32
// dest row m = cm*128 + x*4 + (w>>5), col cc = (w&31)*8 + h
// ---------------------------------------------------------------------------
__global__ __launch_bounds__(256, 2) void k_conv(const float* __restrict__ storage,
                                                 const float* __restrict__ w_cross,
                                                 const float* __restrict__ b_cross) {
    // weights as float4 over ci-groups: wsh[(dx*8+cg)*64 + o] = w[o][cg*4 .. cg*4+3][dx]
    __shared__ float4 wsh[3*8*64];
    __shared__ float  bsh[64];
    int tid = threadIdx.x;
    int bidx = blockIdx.x;                 // b*128 + x*4 + wb
    int b  = bidx >> 7;
    int x  = (bidx >> 2) & 31;
    int wb = bidx & 3;

    for (int i = tid; i < 3*8*64; i += 256) {
        int o    = i & 63;
        int cgdx = i >> 6;                 // 0..23 = dx*8+cg
        int dx = cgdx >> 3, cg = cgdx & 7;
        int ci = cg * 4;
        wsh[i] = make_float4(w_cross[(o*32 + ci+0)*3 + dx],
                             w_cross[(o*32 + ci+1)*3 + dx],
                             w_cross[(o*32 + ci+2)*3 + dx],
                             w_cross[(o*32 + ci+3)*3 + dx]);
    }
    if (tid < 64) bsh[tid] = b_cross[tid];
    __syncthreads();

    int wl = tid >> 3;                     // 0..31
    int h  = tid & 7;
    int w  = wb*32 + wl;

    float acc[64];
#pragma unroll
    for (int o = 0; o < 64; o++) acc[o] = bsh[o];

    for (int dx = 0; dx < 3; dx++) {
        int xx = x + dx - 1;
        if (xx < 0 || xx >= XX) continue;
        const float4* src = (const float4*)(storage + (((b*XX + xx)*HH + h)*WW + w)*CC);
        const float4* wp  = wsh + dx*8*64;
        for (int cg = 0; cg < 8; cg++) {
            float4 iv = src[cg];
            const float4* wo = wp + cg*64;
#pragma unroll
            for (int o = 0; o < 64; o++) {
                float4 wv = wo[o];
                acc[o] += iv.x*wv.x + iv.y*wv.y + iv.z*wv.z + iv.w*wv.w;
            }
        }
    }

    int cc = tid;                          // wl*8 + h == tid
#pragma unroll
    for (int o = 0; o < 64; o++) {
        int cm = o & 31;
        int m  = cm*128 + x*4 + wb;
        float* dst = (o < 32) ? g_V : g_K;
        dst[(b*MM + m)*DD + cc] = acc[o];
    }
}

// ---------------------------------------------------------------------------
// Kernel 3: S = Q @ K^T  per batch.  [128 x 256] @ [256 x 4096]
// CTA: 128(n) x 128(r) tile; k-major shared tiles (stride 132), 8x8 microtile.
// ---------------------------------------------------------------------------
#define STR 132
__global__ __launch_bounds__(256, 2) void k_gemm1() {
    __shared__ float Qs[32*STR];
    __shared__ float Ks[32*STR];
    int tid = threadIdx.x;
    int b  = blockIdx.x >> 5;
    int rb = blockIdx.x & 31;
    int ty = tid >> 4, tx = tid & 15;
    float acc[8][8] = {};
    const float* Qg = g_Q + b*NQ*DD;
    const float* Kg = g_K + (b*MM + rb*128)*DD;

    for (int kt = 0; kt < 8; kt++) {
        int k0 = kt*32;
#pragma unroll
        for (int i = 0; i < 4; i++) {
            int f = tid + i*256;
            int row = f >> 3, kc4 = f & 7;
            float4 qv = *(const float4*)(Qg + row*DD + k0 + kc4*4);
            float4 kv = *(const float4*)(Kg + row*DD + k0 + kc4*4);
            int base = (kc4*4)*STR + row;
            Qs[base        ] = qv.x; Qs[base +   STR] = qv.y;
            Qs[base + 2*STR] = qv.z; Qs[base + 3*STR] = qv.w;
            Ks[base        ] = kv.x; Ks[base +   STR] = kv.y;
            Ks[base + 2*STR] = kv.z; Ks[base + 3*STR] = kv.w;
        }
        __syncthreads();
#pragma unroll 8
        for (int k = 0; k < 32; k++) {
            float4 a0 = *(const float4*)(Qs + k*STR + ty*8);
            float4 a1 = *(const float4*)(Qs + k*STR + ty*8 + 4);
            float4 b0 = *(const float4*)(Ks + k*STR + tx*8);
            float4 b1 = *(const float4*)(Ks + k*STR + tx*8 + 4);
            float av[8] = {a0.x,a0.y,a0.z,a0.w,a1.x,a1.y,a1.z,a1.w};
            float bv[8] = {b0.x,b0.y,b0.z,b0.w,b1.x,b1.y,b1.z,b1.w};
#pragma unroll
            for (int i = 0; i < 8; i++)
#pragma unroll
                for (int j = 0; j < 8; j++) acc[i][j] += av[i]*bv[j];
        }
        __syncthreads();
    }
    float* Sg = g_S + b*NQ*MM + rb*128;
#pragma unroll
    for (int i = 0; i < 8; i++) {
        int row = ty*8 + i;
#pragma unroll
        for (int j4 = 0; j4 < 2; j4++) {
            float4 v = make_float4(acc[i][j4*4+0], acc[i][j4*4+1],
                                   acc[i][j4*4+2], acc[i][j4*4+3]);
            *(float4*)(Sg + row*MM + tx*8 + j4*4) = v;
        }
    }
}

// ---------------------------------------------------------------------------
// Kernel 4: row softmax over 4096 (one CTA per row); also zeroes g_O.
// ---------------------------------------------------------------------------
__global__ __launch_bounds__(256) void k_softmax() {
    __shared__ float red[8], red2[8];
    int tid = threadIdx.x;
    int bid = blockIdx.x;                  // b*128 + n, 512 total
    g_O[bid*256 + tid] = 0.f;              // covers all of g_O exactly

    float* row = g_S + bid*MM;
    float v[16];
    float mx = -1e30f;
#pragma unroll
    for (int i = 0; i < 16; i++) { v[i] = row[tid + i*256]; mx = fmaxf(mx, v[i]); }
#pragma unroll
    for (int s = 16; s; s >>= 1) mx = fmaxf(mx, __shfl_xor_sync(~0u, mx, s));
    if ((tid & 31) == 0) red[tid >> 5] = mx;
    __syncthreads();
    mx = red[0];
#pragma unroll
    for (int i = 1; i < 8; i++) mx = fmaxf(mx, red[i]);

    float sum = 0.f;
#pragma unroll
    for (int i = 0; i < 16; i++) { v[i] = __expf(v[i] - mx); sum += v[i]; }
#pragma unroll
    for (int s = 16; s; s >>= 1) sum += __shfl_xor_sync(~0u, sum, s);
    if ((tid & 31) == 0) red2[tid >> 5] = sum;
    __syncthreads();
    float tot = 0.f;
#pragma unroll
    for (int i = 0; i < 8; i++) tot += red2[i];
    float inv = 1.f / tot;
#pragma unroll
    for (int i = 0; i < 16; i++) row[tid + i*256] = v[i] * inv;
}

// ---------------------------------------------------------------------------
// Kernel 5: O = P @ V per batch, split-K over m with atomicAdd.
// grid = B x 4(cc-tiles of 64) x 8(m-splits of 512). micro 8(n) x 4(cc).
// ---------------------------------------------------------------------------
__global__ __launch_bounds__(256, 2) void k_gemm2() {
    __shared__ float Ps[32*STR];
    __shared__ float Vs[32*68];
    int tid = threadIdx.x;
    int gb = blockIdx.x;
    int b  = gb >> 5;
    int ct = (gb >> 3) & 3;
    int ms = gb & 7;
    int m0  = ms*512;
    int cc0 = ct*64;
    int ty = tid >> 4, tx = tid & 15;
    float acc[8][4] = {};
    const float* Pg = g_S + b*NQ*MM;
    const float* Vg = g_V + b*MM*DD;

    for (int mt = 0; mt < 16; mt++) {
        int mm = m0 + mt*32;
#pragma unroll
        for (int i = 0; i < 4; i++) {
            int f = tid + i*256;
            int row = f >> 3, mc4 = f & 7;
            float4 pv = *(const float4*)(Pg + row*MM + mm + mc4*4);
            int base = (mc4*4)*STR + row;
            Ps[base        ] = pv.x; Ps[base +   STR] = pv.y;
            Ps[base + 2*STR] = pv.z; Ps[base + 3*STR] = pv.w;
        }
#pragma unroll
        for (int i = 0; i < 2; i++) {
            int f = tid + i*256;
            int mrow = f >> 4, c4 = f & 15;
            float4 vv = *(const float4*)(Vg + (mm + mrow)*DD + cc0 + c4*4);
            *(float4*)(Vs + mrow*68 + c4*4) = vv;
        }
        __syncthreads();
#pragma unroll 8
        for (int k = 0; k < 32; k++) {
            float4 a0 = *(const float4*)(Ps + k*STR + ty*8);
            float4 a1 = *(const float4*)(Ps + k*STR + ty*8 + 4);
            float4 bv = *(const float4*)(Vs + k*68 + tx*4);
            float av[8] = {a0.x,a0.y,a0.z,a0.w,a1.x,a1.y,a1.z,a1.w};
#pragma unroll
            for (int i = 0; i < 8; i++) {
                acc[i][0] += av[i]*bv.x; acc[i][1] += av[i]*bv.y;
                acc[i][2] += av[i]*bv.z; acc[i][3] += av[i]*bv.w;
            }
        }
        __syncthreads();
    }
    float* Og = g_O + b*NQ*DD + cc0;
#pragma unroll
    for (int i = 0; i < 8; i++)
#pragma unroll
        for (int j = 0; j < 4; j++)
            atomicAdd(Og + (ty*8 + i)*DD + tx*4 + j, acc[i][j]);
}

// ---------------------------------------------------------------------------
// Kernel 6: scatter to output [B,X,H,W,C].
// out[b,xo,ho,wo,co] = O[b, n=xo*4+((wo>>3)&3), cc=((wo&7)*4+(co>>3))*8+(co&7)]
// (value is independent of ho and of (wo>>5): the x-broadcast of the queries)
// ---------------------------------------------------------------------------
__global__ __launch_bounds__(256) void k_out(float* __restrict__ out) {
    int t = blockIdx.x*256 + threadIdx.x;       // [0, 4M)
    int co = t & 31;
    int wo = (t >> 5) & 127;
    int xo = (t >> 15) & 31;
    int b  = t >> 20;
    int n  = xo*4 + ((wo >> 3) & 3);
    int cc = ((wo & 7)*4 + (co >> 3))*8 + (co & 7);
    out[t] = g_O[(b*NQ + n)*DD + cc];
}

// ---------------------------------------------------------------------------
extern "C" void kernel_launch(void* const* d_in, const int* in_sizes, int n_in,
                              void* d_out, int out_size) {
    const float* storage = (const float*)d_in[0];
    const float* target  = (const float*)d_in[1];
    const float* w_cross = (const float*)d_in[2];
    const float* b_cross = (const float*)d_in[3];
    const float* w_q     = (const float*)d_in[4];
    const float* b_q     = (const float*)d_in[5];
    float* out = (float*)d_out;

    k_q      <<<512,   256>>>(target, w_q, b_q);
    k_conv   <<<512,   256>>>(storage, w_cross, b_cross);
    k_gemm1  <<<128,   256>>>();
    k_softmax<<<512,   256>>>();
    k_gemm2  <<<128,   256>>>();
    k_out    <<<16384, 256>>>(out);
}

// round 2
// speedup vs baseline: 1.5545x; 1.5545x over previous
#include <cuda_runtime.h>
#include <stdint.h>

// Problem constants
#define BB 4
#define XX 32
#define HH 8
#define WW 128
#define CC 32
#define NQ 128          // distinct query rows per batch = C*4
#define MM 4096         // key rows per batch = C*X*4
#define DD 256          // reduction dim = 32*8

// Scratch (device globals; allocation is forbidden)
__device__ float g_Q[BB*NQ*DD];      // [b][n][cc]
__device__ float g_K[BB*MM*DD];      // [b][m][cc]
__device__ float g_V[BB*MM*DD];      // [b][m][cc]
__device__ float g_S[BB*NQ*MM];      // scores -> probs
__device__ float g_O[BB*NQ*DD];      // attention output (pre-scatter)

// ---------------------------------------------------------------------------
// tf32 helpers (3xTF32 split: x = hi + lo, both tf32-rounded)
// ---------------------------------------------------------------------------
__device__ __forceinline__ uint32_t f2tf(float x) {
    uint32_t h; asm("cvt.rna.tf32.f32 %0, %1;" : "=r"(h) : "f"(x)); return h;
}
__device__ __forceinline__ void sts_split(float v, float* ph, float* pl) {
    uint32_t h = f2tf(v);
    float hf = __uint_as_float(h);
    *ph = hf;
    *pl = __uint_as_float(f2tf(v - hf));
}
__device__ __forceinline__ void mma8(float4& d, const uint32_t a[4],
                                     uint32_t b0, uint32_t b1) {
    asm volatile(
        "mma.sync.aligned.m16n8k8.row.col.f32.tf32.tf32.f32 "
        "{%0,%1,%2,%3},{%4,%5,%6,%7},{%8,%9},{%0,%1,%2,%3};"
        : "+f"(d.x), "+f"(d.y), "+f"(d.z), "+f"(d.w)
        : "r"(a[0]), "r"(a[1]), "r"(a[2]), "r"(a[3]), "r"(b0), "r"(b1));
}

// ---------------------------------------------------------------------------
// Kernel 1: Q projection.  Q[b, n=o*4+whi, cc=wlo*8+h] =
//   b_q[o] + sum_c w_q[o,c] * target[b,0,h, whi*32+wlo, c]
// ---------------------------------------------------------------------------
__global__ __launch_bounds__(256) void k_q(const float* __restrict__ target,
                                           const float* __restrict__ w_q,
                                           const float* __restrict__ b_q) {
    int t = blockIdx.x * 256 + threadIdx.x;       // [0, B*128*256)
    int b   = t >> 15;
    int n   = (t >> 8) & 127;
    int cc  = t & 255;
    int o   = n >> 2, whi = n & 3;
    int wlo = cc >> 3, h = cc & 7;
    int w   = whi * 32 + wlo;
    const float4* trow = (const float4*)(target + ((b*HH + h)*WW + w)*CC);
    const float4* wrow = (const float4*)(w_q + o*CC);
    float acc = b_q[o];
#pragma unroll
    for (int i = 0; i < 8; i++) {
        float4 a = trow[i], ww = wrow[i];
        acc += a.x*ww.x + a.y*ww.y + a.z*ww.z + a.w*ww.w;
    }
    g_Q[t] = acc;
}

// ---------------------------------------------------------------------------
// Kernel 2: conv3d (3,1,1) over X as im2col GEMM on tensor cores (3xTF32).
// CTA = (b, w, xhalf): M=128 positions (16 x-values * 8 h), N=64 out-ch, K=96.
// slab smem layout: [si][ci][h] stride 264/x  (si = x_local + dx, 0..17)
// weight smem layout: [k][o]  stride 72
// dest: o<32 -> g_V, o>=32 -> g_K;  m=(o&31)*128 + x*4 + (w>>5), cc=(w&31)*8+h
// ---------------------------------------------------------------------------
#define CONV_SMEM_FLOATS (2*18*264 + 2*96*72 + 64)
__global__ __launch_bounds__(256) void k_conv(const float* __restrict__ storage,
                                              const float* __restrict__ w_cross,
                                              const float* __restrict__ b_cross) {
    extern __shared__ float sm[];
    float* Sh  = sm;                    // 18*264
    float* Sl  = Sh + 18*264;
    float* Wh  = Sl + 18*264;           // 96*72
    float* Wl  = Wh + 96*72;
    float* bsh = Wl + 96*72;            // 64

    int tid  = threadIdx.x;
    int bidx = blockIdx.x;              // b*256 + w*2 + xh
    int b  = bidx >> 8;
    int w  = (bidx >> 1) & 127;
    int xh = bidx & 1;
    int x0 = xh * 16;

    // weights -> shared, split hi/lo, layout [k][o] stride 72
    for (int i = tid; i < 6144; i += 256) {
        int o = i / 96, k = i % 96;
        int dx = k >> 5, ci = k & 31;
        float v = w_cross[(o*32 + ci)*3 + dx];
        sts_split(v, Wh + k*72 + o, Wl + k*72 + o);
    }
    if (tid < 64) bsh[tid] = b_cross[tid];

    // input slab (with halo + zero pad), split hi/lo
    for (int i = tid; i < 18*64; i += 256) {
        int si = i >> 6, r = i & 63;
        int c4 = (r & 7)*4, h = r >> 3;
        int xx = x0 - 1 + si;
        float4 v = make_float4(0.f, 0.f, 0.f, 0.f);
        if (xx >= 0 && xx < XX)
            v = *(const float4*)(storage + (((b*XX + xx)*HH + h)*WW + w)*CC + c4);
        float* ph = Sh + si*264 + c4*8 + h;
        float* pl = Sl + si*264 + c4*8 + h;
        sts_split(v.x, ph +  0, pl +  0);
        sts_split(v.y, ph +  8, pl +  8);
        sts_split(v.z, ph + 16, pl + 16);
        sts_split(v.w, ph + 24, pl + 24);
    }
    __syncthreads();

    int lane = tid & 31, ww = tid >> 5;
    int lr = lane >> 2, lc = lane & 3;
    int wm = ww & 3, wn = ww >> 2;      // 4 m-blocks x 2 n-blocks; warp tile 32x32
    float4 acc[2][4];
#pragma unroll
    for (int i = 0; i < 2; i++)
#pragma unroll
        for (int j = 0; j < 4; j++) acc[i][j] = make_float4(0.f,0.f,0.f,0.f);

#pragma unroll
    for (int ksl = 0; ksl < 12; ksl++) {
        int k0 = ksl*8;
        int dx = k0 >> 5, cib = k0 & 31;
        uint32_t ah[2][4], al[2][4];
#pragma unroll
        for (int mt = 0; mt < 2; mt++) {
            int rowb = wm*32 + mt*16;
            int xl = rowb >> 3;                  // rows rowb..+15 -> xl, xl+1
            const float* p = Sh + (xl + dx)*264 + (cib + lc)*8 + lr;
            ah[mt][0] = __float_as_uint(p[0]);
            ah[mt][1] = __float_as_uint(p[264]);
            ah[mt][2] = __float_as_uint(p[32]);
            ah[mt][3] = __float_as_uint(p[264+32]);
            const float* q = Sl + (xl + dx)*264 + (cib + lc)*8 + lr;
            al[mt][0] = __float_as_uint(q[0]);
            al[mt][1] = __float_as_uint(q[264]);
            al[mt][2] = __float_as_uint(q[32]);
            al[mt][3] = __float_as_uint(q[264+32]);
        }
#pragma unroll
        for (int nt = 0; nt < 4; nt++) {
            int nb = wn*32 + nt*8;
            const float* p = Wh + (k0 + lc)*72 + nb + lr;
            uint32_t bh0 = __float_as_uint(p[0]);
            uint32_t bh1 = __float_as_uint(p[4*72]);
            const float* q = Wl + (k0 + lc)*72 + nb + lr;
            uint32_t bl0 = __float_as_uint(q[0]);
            uint32_t bl1 = __float_as_uint(q[4*72]);
#pragma unroll
            for (int mt = 0; mt < 2; mt++) {
                mma8(acc[mt][nt], ah[mt], bh0, bh1);
                mma8(acc[mt][nt], ah[mt], bl0, bl1);
                mma8(acc[mt][nt], al[mt], bh0, bh1);
            }
        }
    }

    // epilogue: add bias, scatter to g_K / g_V
    int wb = w >> 5, ccb = (w & 31)*8;
#pragma unroll
    for (int mt = 0; mt < 2; mt++) {
        int rowb = wm*32 + mt*16;
        int x = x0 + (rowb >> 3);
        int h = lr;
#pragma unroll
        for (int nt = 0; nt < 4; nt++) {
            int o0 = wn*32 + nt*8 + lc*2;
            float4 d = acc[mt][nt];
            {
                float v0 = d.x + bsh[o0], v1 = d.y + bsh[o0+1];
                float* d0 = (o0     < 32) ? g_V : g_K;
                float* d1 = (o0 + 1 < 32) ? g_V : g_K;
                d0[(b*MM + (o0&31)*128     + x*4 + wb)*DD + ccb + h] = v0;
                d1[(b*MM + ((o0+1)&31)*128 + x*4 + wb)*DD + ccb + h] = v1;
            }
            {
                float v0 = d.z + bsh[o0], v1 = d.w + bsh[o0+1];
                float* d0 = (o0     < 32) ? g_V : g_K;
                float* d1 = (o0 + 1 < 32) ? g_V : g_K;
                d0[(b*MM + (o0&31)*128     + (x+1)*4 + wb)*DD + ccb + h] = v0;
                d1[(b*MM + ((o0+1)&31)*128 + (x+1)*4 + wb)*DD + ccb + h] = v1;
            }
        }
    }
}

// ---------------------------------------------------------------------------
// Kernel 3: S = Q @ K^T per batch (3xTF32).  CTA tile 128m x 128n, K=256.
// smem: Q/K hi+lo tiles [128][32] stride 36.
// ---------------------------------------------------------------------------
#define G1_SMEM_FLOATS (4*128*36)
__global__ __launch_bounds__(256) void k_gemm1() {
    extern __shared__ float sm[];
    float* Qh = sm;
    float* Ql = Qh + 128*36;
    float* Kh = Ql + 128*36;
    float* Kl = Kh + 128*36;

    int tid = threadIdx.x;
    int b  = blockIdx.x >> 5;
    int nb = blockIdx.x & 31;
    const float* Qg = g_Q + b*NQ*DD;
    const float* Kg = g_K + (b*MM + nb*128)*DD;

    int lane = tid & 31, ww = tid >> 5;
    int lr = lane >> 2, lc = lane & 3;
    int wm = ww & 1, wn = ww >> 1;            // 2m x 4n; warp tile 64x32
    float4 acc[4][4];
#pragma unroll
    for (int i = 0; i < 4; i++)
#pragma unroll
        for (int j = 0; j < 4; j++) acc[i][j] = make_float4(0.f,0.f,0.f,0.f);

    for (int kt = 0; kt < 8; kt++) {
        int k0 = kt*32;
        __syncthreads();
#pragma unroll
        for (int i = 0; i < 4; i++) {
            int f = tid + i*256;
            int row = f >> 3, c4 = (f & 7)*4;
            float4 qv = *(const float4*)(Qg + row*DD + k0 + c4);
            float4 kv = *(const float4*)(Kg + row*DD + k0 + c4);
            float* qh = Qh + row*36 + c4; float* ql = Ql + row*36 + c4;
            sts_split(qv.x, qh+0, ql+0); sts_split(qv.y, qh+1, ql+1);
            sts_split(qv.z, qh+2, ql+2); sts_split(qv.w, qh+3, ql+3);
            float* kh = Kh + row*36 + c4; float* kl = Kl + row*36 + c4;
            sts_split(kv.x, kh+0, kl+0); sts_split(kv.y, kh+1, kl+1);
            sts_split(kv.z, kh+2, kl+2); sts_split(kv.w, kh+3, kl+3);
        }
        __syncthreads();
#pragma unroll
        for (int ks = 0; ks < 4; ks++) {
            int kk = ks*8;
            uint32_t ah[4][4], al[4][4];
#pragma unroll
            for (int mt = 0; mt < 4; mt++) {
                const float* p = Qh + (wm*64 + mt*16 + lr)*36 + kk + lc;
                ah[mt][0] = __float_as_uint(p[0]);
                ah[mt][1] = __float_as_uint(p[8*36]);
                ah[mt][2] = __float_as_uint(p[4]);
                ah[mt][3] = __float_as_uint(p[8*36+4]);
                const float* q = Ql + (wm*64 + mt*16 + lr)*36 + kk + lc;
                al[mt][0] = __float_as_uint(q[0]);
                al[mt][1] = __float_as_uint(q[8*36]);
                al[mt][2] = __float_as_uint(q[4]);
                al[mt][3] = __float_as_uint(q[8*36+4]);
            }
#pragma unroll
            for (int nt = 0; nt < 4; nt++) {
                const float* p = Kh + (wn*32 + nt*8 + lr)*36 + kk + lc;
                uint32_t bh0 = __float_as_uint(p[0]);
                uint32_t bh1 = __float_as_uint(p[4]);
                const float* q = Kl + (wn*32 + nt*8 + lr)*36 + kk + lc;
                uint32_t bl0 = __float_as_uint(q[0]);
                uint32_t bl1 = __float_as_uint(q[4]);
#pragma unroll
                for (int mt = 0; mt < 4; mt++) {
                    mma8(acc[mt][nt], ah[mt], bh0, bh1);
                    mma8(acc[mt][nt], ah[mt], bl0, bl1);
                    mma8(acc[mt][nt], al[mt], bh0, bh1);
                }
            }
        }
    }

    float* Sg = g_S + b*NQ*MM + nb*128;
#pragma unroll
    for (int mt = 0; mt < 4; mt++) {
#pragma unroll
        for (int nt = 0; nt < 4; nt++) {
            int row = wm*64 + mt*16 + lr;
            int col = wn*32 + nt*8 + lc*2;
            float4 d = acc[mt][nt];
            *(float2*)(Sg + row*MM + col)     = make_float2(d.x, d.y);
            *(float2*)(Sg + (row+8)*MM + col) = make_float2(d.z, d.w);
        }
    }
}

// ---------------------------------------------------------------------------
// Kernel 4: row softmax over 4096 (one CTA per row); also zeroes g_O.
// ---------------------------------------------------------------------------
__global__ __launch_bounds__(256) void k_softmax() {
    __shared__ float red[8], red2[8];
    int tid = threadIdx.x;
    int bid = blockIdx.x;                  // b*128 + n, 512 total
    g_O[bid*256 + tid] = 0.f;              // covers all of g_O exactly

    float* row = g_S + bid*MM;
    float v[16];
    float mx = -1e30f;
#pragma unroll
    for (int i = 0; i < 16; i++) { v[i] = row[tid + i*256]; mx = fmaxf(mx, v[i]); }
#pragma unroll
    for (int s = 16; s; s >>= 1) mx = fmaxf(mx, __shfl_xor_sync(~0u, mx, s));
    if ((tid & 31) == 0) red[tid >> 5] = mx;
    __syncthreads();
    mx = red[0];
#pragma unroll
    for (int i = 1; i < 8; i++) mx = fmaxf(mx, red[i]);

    float sum = 0.f;
#pragma unroll
    for (int i = 0; i < 16; i++) { v[i] = __expf(v[i] - mx); sum += v[i]; }
#pragma unroll
    for (int s = 16; s; s >>= 1) sum += __shfl_xor_sync(~0u, sum, s);
    if ((tid & 31) == 0) red2[tid >> 5] = sum;
    __syncthreads();
    float tot = 0.f;
#pragma unroll
    for (int i = 0; i < 8; i++) tot += red2[i];
    float inv = 1.f / tot;
#pragma unroll
    for (int i = 0; i < 16; i++) row[tid + i*256] = v[i] * inv;
}

// ---------------------------------------------------------------------------
// Kernel 5: O = P @ V per batch (3xTF32), split-K(m) with atomicAdd.
// grid = b(4) x nb(2: n-tiles of 128) x ks(16: k-splits of 256).
// smem: P hi/lo [128][32] str 36;  V hi/lo [32][128] str 136.
// ---------------------------------------------------------------------------
#define G2_SMEM_FLOATS (2*128*36 + 2*32*136)
__global__ __launch_bounds__(256) void k_gemm2() {
    extern __shared__ float sm[];
    float* Ph = sm;                    // 128*36
    float* Pl = Ph + 128*36;
    float* Vh = Pl + 128*36;           // 32*136
    float* Vl = Vh + 32*136;

    int tid = threadIdx.x;
    int b    = blockIdx.x >> 5;
    int rest = blockIdx.x & 31;
    int nb   = rest >> 4;              // 0..1
    int ks   = rest & 15;              // 0..15
    int m0   = ks*256;
    const float* Pg = g_S + b*NQ*MM;
    const float* Vg = g_V + b*MM*DD;

    int lane = tid & 31, ww = tid >> 5;
    int lr = lane >> 2, lc = lane & 3;
    int wm = ww & 1, wn = ww >> 1;     // 2m x 4n; warp tile 64x32
    float4 acc[4][4];
#pragma unroll
    for (int i = 0; i < 4; i++)
#pragma unroll
        for (int j = 0; j < 4; j++) acc[i][j] = make_float4(0.f,0.f,0.f,0.f);

    for (int kt = 0; kt < 8; kt++) {
        int kbase = m0 + kt*32;
        __syncthreads();
#pragma unroll
        for (int i = 0; i < 4; i++) {
            int f = tid + i*256;
            int row = f >> 3, c4 = (f & 7)*4;
            float4 pv = *(const float4*)(Pg + row*MM + kbase + c4);
            float* ph = Ph + row*36 + c4; float* pl = Pl + row*36 + c4;
            sts_split(pv.x, ph+0, pl+0); sts_split(pv.y, ph+1, pl+1);
            sts_split(pv.z, ph+2, pl+2); sts_split(pv.w, ph+3, pl+3);
        }
#pragma unroll
        for (int i = 0; i < 4; i++) {
            int f = tid + i*256;
            int kr = f >> 5, c4 = (f & 31)*4;
            float4 vv = *(const float4*)(Vg + (kbase + kr)*DD + nb*128 + c4);
            float* vh = Vh + kr*136 + c4; float* vl = Vl + kr*136 + c4;
            sts_split(vv.x, vh+0, vl+0); sts_split(vv.y, vh+1, vl+1);
            sts_split(vv.z, vh+2, vl+2); sts_split(vv.w, vh+3, vl+3);
        }
        __syncthreads();
#pragma unroll
        for (int kk8 = 0; kk8 < 4; kk8++) {
            int kk = kk8*8;
            uint32_t ah[4][4], al[4][4];
#pragma unroll
            for (int mt = 0; mt < 4; mt++) {
                const float* p = Ph + (wm*64 + mt*16 + lr)*36 + kk + lc;
                ah[mt][0] = __float_as_uint(p[0]);
                ah[mt][1] = __float_as_uint(p[8*36]);
                ah[mt][2] = __float_as_uint(p[4]);
                ah[mt][3] = __float_as_uint(p[8*36+4]);
                const float* q = Pl + (wm*64 + mt*16 + lr)*36 + kk + lc;
                al[mt][0] = __float_as_uint(q[0]);
                al[mt][1] = __float_as_uint(q[8*36]);
                al[mt][2] = __float_as_uint(q[4]);
                al[mt][3] = __float_as_uint(q[8*36+4]);
            }
#pragma unroll
            for (int nt = 0; nt < 4; nt++) {
                const float* p = Vh + (kk + lc)*136 + wn*32 + nt*8 + lr;
                uint32_t bh0 = __float_as_uint(p[0]);
                uint32_t bh1 = __float_as_uint(p[4*136]);
                const float* q = Vl + (kk + lc)*136 + wn*32 + nt*8 + lr;
                uint32_t bl0 = __float_as_uint(q[0]);
                uint32_t bl1 = __float_as_uint(q[4*136]);
#pragma unroll
                for (int mt = 0; mt < 4; mt++) {
                    mma8(acc[mt][nt], ah[mt], bh0, bh1);
                    mma8(acc[mt][nt], ah[mt], bl0, bl1);
                    mma8(acc[mt][nt], al[mt], bh0, bh1);
                }
            }
        }
    }

    float* Og = g_O + b*NQ*DD + nb*128;
#pragma unroll
    for (int mt = 0; mt < 4; mt++) {
#pragma unroll
        for (int nt = 0; nt < 4; nt++) {
            int row = wm*64 + mt*16 + lr;
            int col = wn*32 + nt*8 + lc*2;
            float4 d = acc[mt][nt];
            atomicAdd(Og + row*DD + col,       d.x);
            atomicAdd(Og + row*DD + col + 1,   d.y);
            atomicAdd(Og + (row+8)*DD + col,   d.z);
            atomicAdd(Og + (row+8)*DD + col+1, d.w);
        }
    }
}

// ---------------------------------------------------------------------------
// Kernel 6: scatter to output [B,X,H,W,C].
// ---------------------------------------------------------------------------
__global__ __launch_bounds__(256) void k_out(float* __restrict__ out) {
    int t = blockIdx.x*256 + threadIdx.x;       // [0, 4M)
    int co = t & 31;
    int wo = (t >> 5) & 127;
    int xo = (t >> 15) & 31;
    int b  = t >> 20;
    int n  = xo*4 + ((wo >> 3) & 3);
    int cc = ((wo & 7)*4 + (co >> 3))*8 + (co & 7);
    out[t] = g_O[(b*NQ + n)*DD + cc];
}

// ---------------------------------------------------------------------------
extern "C" void kernel_launch(void* const* d_in, const int* in_sizes, int n_in,
                              void* d_out, int out_size) {
    const float* storage = (const float*)d_in[0];
    const float* target  = (const float*)d_in[1];
    const float* w_cross = (const float*)d_in[2];
    const float* b_cross = (const float*)d_in[3];
    const float* w_q     = (const float*)d_in[4];
    const float* b_q     = (const float*)d_in[5];
    float* out = (float*)d_out;

    cudaFuncSetAttribute(k_conv,  cudaFuncAttributeMaxDynamicSharedMemorySize,
                         CONV_SMEM_FLOATS * 4);
    cudaFuncSetAttribute(k_gemm1, cudaFuncAttributeMaxDynamicSharedMemorySize,
                         G1_SMEM_FLOATS * 4);
    cudaFuncSetAttribute(k_gemm2, cudaFuncAttributeMaxDynamicSharedMemorySize,
                         G2_SMEM_FLOATS * 4);

    k_q      <<<512,   256>>>(target, w_q, b_q);
    k_conv   <<<1024,  256, CONV_SMEM_FLOATS*4>>>(storage, w_cross, b_cross);
    k_gemm1  <<<128,   256, G1_SMEM_FLOATS*4>>>();
    k_softmax<<<512,   256>>>();
    k_gemm2  <<<128,   256, G2_SMEM_FLOATS*4>>>();
    k_out    <<<16384, 256>>>(out);
}

// round 3
// speedup vs baseline: 1.7607x; 1.1326x over previous
#include <cuda_runtime.h>
#include <stdint.h>

// Problem constants
#define BB 4
#define XX 32
#define HH 8
#define WW 128
#define CC 32
#define NQ 128          // distinct query rows per batch = C*4
#define MM 4096         // key rows per batch = C*X*4
#define DD 256          // reduction dim = 32*8

// Scratch (device globals; allocation is forbidden)
__device__ __align__(16) float g_Qh[BB*NQ*DD];
__device__ __align__(16) float g_Ql[BB*NQ*DD];
__device__ __align__(16) float g_K [BB*MM*DD];
__device__ __align__(16) float g_V [BB*MM*DD];
__device__ __align__(16) float g_Eh[BB*NQ*MM];   // exp(S) hi
__device__ __align__(16) float g_El[BB*NQ*MM];   // exp(S) lo
__device__ __align__(16) float g_O [BB*NQ*DD];   // unnormalized attention out
__device__ __align__(16) float g_rowsum[BB*NQ];
__device__ __align__(16) float g_Wh[96*72];      // presplit conv weights [k][o]
__device__ __align__(16) float g_Wl[96*72];

// ---------------------------------------------------------------------------
// tf32 helpers (3xTF32 split: x = hi + lo, both tf32-rounded)
// ---------------------------------------------------------------------------
__device__ __forceinline__ uint32_t f2tf(float x) {
    uint32_t h; asm("cvt.rna.tf32.f32 %0, %1;" : "=r"(h) : "f"(x)); return h;
}
__device__ __forceinline__ void sts_split(float v, float* ph, float* pl) {
    uint32_t h = f2tf(v);
    float hf = __uint_as_float(h);
    *ph = hf;
    *pl = __uint_as_float(f2tf(v - hf));
}
__device__ __forceinline__ void mma8(float4& d, const uint32_t a[4],
                                     uint32_t b0, uint32_t b1) {
    asm volatile(
        "mma.sync.aligned.m16n8k8.row.col.f32.tf32.tf32.f32 "
        "{%0,%1,%2,%3},{%4,%5,%6,%7},{%8,%9},{%0,%1,%2,%3};"
        : "+f"(d.x), "+f"(d.y), "+f"(d.z), "+f"(d.w)
        : "r"(a[0]), "r"(a[1]), "r"(a[2]), "r"(a[3]), "r"(b0), "r"(b1));
}

// ---------------------------------------------------------------------------
// Kernel 1: Q projection (presplit) + zero g_O/g_rowsum + presplit conv weights
// ---------------------------------------------------------------------------
__global__ __launch_bounds__(256) void k_q(const float* __restrict__ target,
                                           const float* __restrict__ w_q,
                                           const float* __restrict__ b_q,
                                           const float* __restrict__ w_cross) {
    int t = blockIdx.x * 256 + threadIdx.x;       // [0, 131072)
    g_O[t] = 0.f;
    if (t < BB*NQ) g_rowsum[t] = 0.f;
    if (t < 96*72) {
        int k = t / 72, o = t - k*72;
        float v = (o < 64) ? w_cross[(o*32 + (k & 31))*3 + (k >> 5)] : 0.f;
        sts_split(v, &g_Wh[t], &g_Wl[t]);
    }

    int b   = t >> 15;
    int n   = (t >> 8) & 127;
    int cc  = t & 255;
    int o   = n >> 2, whi = n & 3;
    int wlo = cc >> 3, h = cc & 7;
    int w   = whi * 32 + wlo;
    const float4* trow = (const float4*)(target + ((b*HH + h)*WW + w)*CC);
    const float4* wrow = (const float4*)(w_q + o*CC);
    float acc = b_q[o];
#pragma unroll
    for (int i = 0; i < 8; i++) {
        float4 a = trow[i], ww = wrow[i];
        acc += a.x*ww.x + a.y*ww.y + a.z*ww.z + a.w*ww.w;
    }
    sts_split(acc, &g_Qh[t], &g_Ql[t]);
}

// ---------------------------------------------------------------------------
// Kernel 2: conv3d (3,1,1) over X as im2col GEMM on tensor cores (3xTF32).
// CTA = (b, w, xhalf): M=128 positions (16 x * 8 h), N=64 out-ch, K=96.
// Weights come presplit from g_Wh/g_Wl ([k][o] stride 72) via coalesced copy.
// ---------------------------------------------------------------------------
#define CONV_SMEM_FLOATS (2*18*264 + 2*96*72 + 64)
__global__ __launch_bounds__(256) void k_conv(const float* __restrict__ storage,
                                              const float* __restrict__ b_cross) {
    extern __shared__ float sm[];
    float* Sh  = sm;                    // 18*264
    float* Sl  = Sh + 18*264;
    float* Wh  = Sl + 18*264;           // 96*72
    float* Wl  = Wh + 96*72;
    float* bsh = Wl + 96*72;            // 64

    int tid  = threadIdx.x;
    int bidx = blockIdx.x;              // b*256 + w*2 + xh
    int b  = bidx >> 8;
    int w  = (bidx >> 1) & 127;
    int xh = bidx & 1;
    int x0 = xh * 16;

    // coalesced float4 copy of presplit weights (96*72 = 6912 floats = 1728 f4)
    {
        const float4* sh4 = (const float4*)g_Wh;
        const float4* sl4 = (const float4*)g_Wl;
        float4* dh4 = (float4*)Wh;
        float4* dl4 = (float4*)Wl;
        for (int i = tid; i < 1728; i += 256) { dh4[i] = sh4[i]; dl4[i] = sl4[i]; }
    }
    if (tid < 64) bsh[tid] = b_cross[tid];

    // input slab (with halo + zero pad), split hi/lo; layout [si][ci*8+h] str 264
    for (int i = tid; i < 18*64; i += 256) {
        int si = i >> 6, r = i & 63;
        int c4 = (r & 7)*4, h = r >> 3;
        int xx = x0 - 1 + si;
        float4 v = make_float4(0.f, 0.f, 0.f, 0.f);
        if (xx >= 0 && xx < XX)
            v = *(const float4*)(storage + (((b*XX + xx)*HH + h)*WW + w)*CC + c4);
        float* ph = Sh + si*264 + c4*8 + h;
        float* pl = Sl + si*264 + c4*8 + h;
        sts_split(v.x, ph +  0, pl +  0);
        sts_split(v.y, ph +  8, pl +  8);
        sts_split(v.z, ph + 16, pl + 16);
        sts_split(v.w, ph + 24, pl + 24);
    }
    __syncthreads();

    int lane = tid & 31, ww = tid >> 5;
    int lr = lane >> 2, lc = lane & 3;
    int wm = ww & 3, wn = ww >> 2;      // 4 m-blocks x 2 n-blocks; warp tile 32x32
    float4 acc[2][4];
#pragma unroll
    for (int i = 0; i < 2; i++)
#pragma unroll
        for (int j = 0; j < 4; j++) acc[i][j] = make_float4(0.f,0.f,0.f,0.f);

#pragma unroll
    for (int ksl = 0; ksl < 12; ksl++) {
        int k0 = ksl*8;
        int dx = k0 >> 5, cib = k0 & 31;
        uint32_t ah[2][4], al[2][4];
#pragma unroll
        for (int mt = 0; mt < 2; mt++) {
            int rowb = wm*32 + mt*16;
            int xl = rowb >> 3;
            const float* p = Sh + (xl + dx)*264 + (cib + lc)*8 + lr;
            ah[mt][0] = __float_as_uint(p[0]);
            ah[mt][1] = __float_as_uint(p[264]);
            ah[mt][2] = __float_as_uint(p[32]);
            ah[mt][3] = __float_as_uint(p[264+32]);
            const float* q = Sl + (xl + dx)*264 + (cib + lc)*8 + lr;
            al[mt][0] = __float_as_uint(q[0]);
            al[mt][1] = __float_as_uint(q[264]);
            al[mt][2] = __float_as_uint(q[32]);
            al[mt][3] = __float_as_uint(q[264+32]);
        }
#pragma unroll
        for (int nt = 0; nt < 4; nt++) {
            int nb = wn*32 + nt*8;
            const float* p = Wh + (k0 + lc)*72 + nb + lr;
            uint32_t bh0 = __float_as_uint(p[0]);
            uint32_t bh1 = __float_as_uint(p[4*72]);
            const float* q = Wl + (k0 + lc)*72 + nb + lr;
            uint32_t bl0 = __float_as_uint(q[0]);
            uint32_t bl1 = __float_as_uint(q[4*72]);
#pragma unroll
            for (int mt = 0; mt < 2; mt++) {
                mma8(acc[mt][nt], ah[mt], bh0, bh1);
                mma8(acc[mt][nt], ah[mt], bl0, bl1);
                mma8(acc[mt][nt], al[mt], bh0, bh1);
            }
        }
    }

    // epilogue: add bias, scatter to g_K / g_V
    int wb = w >> 5, ccb = (w & 31)*8;
#pragma unroll
    for (int mt = 0; mt < 2; mt++) {
        int rowb = wm*32 + mt*16;
        int x = x0 + (rowb >> 3);
        int h = lr;
#pragma unroll
        for (int nt = 0; nt < 4; nt++) {
            int o0 = wn*32 + nt*8 + lc*2;
            float4 d = acc[mt][nt];
            {
                float v0 = d.x + bsh[o0], v1 = d.y + bsh[o0+1];
                float* d0 = (o0     < 32) ? g_V : g_K;
                float* d1 = (o0 + 1 < 32) ? g_V : g_K;
                d0[(b*MM + (o0&31)*128     + x*4 + wb)*DD + ccb + h] = v0;
                d1[(b*MM + ((o0+1)&31)*128 + x*4 + wb)*DD + ccb + h] = v1;
            }
            {
                float v0 = d.z + bsh[o0], v1 = d.w + bsh[o0+1];
                float* d0 = (o0     < 32) ? g_V : g_K;
                float* d1 = (o0 + 1 < 32) ? g_V : g_K;
                d0[(b*MM + (o0&31)*128     + (x+1)*4 + wb)*DD + ccb + h] = v0;
                d1[(b*MM + ((o0+1)&31)*128 + (x+1)*4 + wb)*DD + ccb + h] = v1;
            }
        }
    }
}

// ---------------------------------------------------------------------------
// Kernel 3: S = Q @ K^T per batch (3xTF32), fused exp + rowsum epilogue.
// Writes E = exp(S) presplit (g_Eh/g_El); atomically accumulates g_rowsum.
// ---------------------------------------------------------------------------
#define G1_SMEM_FLOATS (4*128*36 + 128)
__global__ __launch_bounds__(256) void k_gemm1() {
    extern __shared__ float sm[];
    float* Qh = sm;
    float* Ql = Qh + 128*36;
    float* Kh = Ql + 128*36;
    float* Kl = Kh + 128*36;
    float* srow = Kl + 128*36;          // 128 row partial sums

    int tid = threadIdx.x;
    int b  = blockIdx.x >> 5;
    int nb = blockIdx.x & 31;
    const float* Qgh = g_Qh + b*NQ*DD;
    const float* Qgl = g_Ql + b*NQ*DD;
    const float* Kg  = g_K + (b*MM + nb*128)*DD;

    int lane = tid & 31, ww = tid >> 5;
    int lr = lane >> 2, lc = lane & 3;
    int wm = ww & 1, wn = ww >> 1;            // 2m x 4n; warp tile 64x32
    float4 acc[4][4];
#pragma unroll
    for (int i = 0; i < 4; i++)
#pragma unroll
        for (int j = 0; j < 4; j++) acc[i][j] = make_float4(0.f,0.f,0.f,0.f);

    for (int kt = 0; kt < 8; kt++) {
        int k0 = kt*32;
        __syncthreads();
#pragma unroll
        for (int i = 0; i < 4; i++) {
            int f = tid + i*256;
            int row = f >> 3, c4 = (f & 7)*4;
            *(float4*)(Qh + row*36 + c4) = *(const float4*)(Qgh + row*DD + k0 + c4);
            *(float4*)(Ql + row*36 + c4) = *(const float4*)(Qgl + row*DD + k0 + c4);
            float4 kv = *(const float4*)(Kg + row*DD + k0 + c4);
            float* kh = Kh + row*36 + c4; float* kl = Kl + row*36 + c4;
            sts_split(kv.x, kh+0, kl+0); sts_split(kv.y, kh+1, kl+1);
            sts_split(kv.z, kh+2, kl+2); sts_split(kv.w, kh+3, kl+3);
        }
        __syncthreads();
#pragma unroll
        for (int ks = 0; ks < 4; ks++) {
            int kk = ks*8;
            uint32_t ah[4][4], al[4][4];
#pragma unroll
            for (int mt = 0; mt < 4; mt++) {
                const float* p = Qh + (wm*64 + mt*16 + lr)*36 + kk + lc;
                ah[mt][0] = __float_as_uint(p[0]);
                ah[mt][1] = __float_as_uint(p[8*36]);
                ah[mt][2] = __float_as_uint(p[4]);
                ah[mt][3] = __float_as_uint(p[8*36+4]);
                const float* q = Ql + (wm*64 + mt*16 + lr)*36 + kk + lc;
                al[mt][0] = __float_as_uint(q[0]);
                al[mt][1] = __float_as_uint(q[8*36]);
                al[mt][2] = __float_as_uint(q[4]);
                al[mt][3] = __float_as_uint(q[8*36+4]);
            }
#pragma unroll
            for (int nt = 0; nt < 4; nt++) {
                const float* p = Kh + (wn*32 + nt*8 + lr)*36 + kk + lc;
                uint32_t bh0 = __float_as_uint(p[0]);
                uint32_t bh1 = __float_as_uint(p[4]);
                const float* q = Kl + (wn*32 + nt*8 + lr)*36 + kk + lc;
                uint32_t bl0 = __float_as_uint(q[0]);
                uint32_t bl1 = __float_as_uint(q[4]);
#pragma unroll
                for (int mt = 0; mt < 4; mt++) {
                    mma8(acc[mt][nt], ah[mt], bh0, bh1);
                    mma8(acc[mt][nt], ah[mt], bl0, bl1);
                    mma8(acc[mt][nt], al[mt], bh0, bh1);
                }
            }
        }
    }

    // epilogue: E = exp(S), presplit store, rowsum accumulation
    if (tid < 128) srow[tid] = 0.f;
    __syncthreads();

    float* Egh = g_Eh + b*NQ*MM + nb*128;
    float* Egl = g_El + b*NQ*MM + nb*128;
    float rs[8] = {0.f,0.f,0.f,0.f,0.f,0.f,0.f,0.f};
#pragma unroll
    for (int mt = 0; mt < 4; mt++) {
#pragma unroll
        for (int nt = 0; nt < 4; nt++) {
            int row = wm*64 + mt*16 + lr;
            int col = wn*32 + nt*8 + lc*2;
            float4 d = acc[mt][nt];
            float e0 = __expf(d.x), e1 = __expf(d.y);
            float e2 = __expf(d.z), e3 = __expf(d.w);
            rs[mt*2+0] += e0 + e1;
            rs[mt*2+1] += e2 + e3;
            uint32_t h0 = f2tf(e0), h1 = f2tf(e1), h2 = f2tf(e2), h3 = f2tf(e3);
            float hf0 = __uint_as_float(h0), hf1 = __uint_as_float(h1);
            float hf2 = __uint_as_float(h2), hf3 = __uint_as_float(h3);
            *(float2*)(Egh + row*MM + col)     = make_float2(hf0, hf1);
            *(float2*)(Egh + (row+8)*MM + col) = make_float2(hf2, hf3);
            *(float2*)(Egl + row*MM + col)     =
                make_float2(__uint_as_float(f2tf(e0 - hf0)),
                            __uint_as_float(f2tf(e1 - hf1)));
            *(float2*)(Egl + (row+8)*MM + col) =
                make_float2(__uint_as_float(f2tf(e2 - hf2)),
                            __uint_as_float(f2tf(e3 - hf3)));
        }
    }
#pragma unroll
    for (int i = 0; i < 8; i++) {
        rs[i] += __shfl_xor_sync(~0u, rs[i], 1);
        rs[i] += __shfl_xor_sync(~0u, rs[i], 2);
    }
    if (lc == 0) {
#pragma unroll
        for (int i = 0; i < 8; i++)
            atomicAdd(&srow[wm*64 + (i >> 1)*16 + (i & 1)*8 + lr], rs[i]);
    }
    __syncthreads();
    if (tid < 128) atomicAdd(&g_rowsum[b*128 + tid], srow[tid]);
}

// ---------------------------------------------------------------------------
// Kernel 4: O += E @ V per batch (3xTF32), split-K(m) with atomicAdd.
// E comes presplit -> pure float4 load/store staging, no cvt.
// ---------------------------------------------------------------------------
#define G2_SMEM_FLOATS (2*128*36 + 2*32*136)
__global__ __launch_bounds__(256) void k_gemm2() {
    extern __shared__ float sm[];
    float* Ph = sm;                    // 128*36
    float* Pl = Ph + 128*36;
    float* Vh = Pl + 128*36;           // 32*136
    float* Vl = Vh + 32*136;

    int tid = threadIdx.x;
    int b    = blockIdx.x >> 5;
    int rest = blockIdx.x & 31;
    int nb   = rest >> 4;              // 0..1
    int ks   = rest & 15;              // 0..15
    int m0   = ks*256;
    const float* Egh = g_Eh + b*NQ*MM;
    const float* Egl = g_El + b*NQ*MM;
    const float* Vg  = g_V + b*MM*DD;

    int lane = tid & 31, ww = tid >> 5;
    int lr = lane >> 2, lc = lane & 3;
    int wm = ww & 1, wn = ww >> 1;     // 2m x 4n; warp tile 64x32
    float4 acc[4][4];
#pragma unroll
    for (int i = 0; i < 4; i++)
#pragma unroll
        for (int j = 0; j < 4; j++) acc[i][j] = make_float4(0.f,0.f,0.f,0.f);

    for (int kt = 0; kt < 8; kt++) {
        int kbase = m0 + kt*32;
        __syncthreads();
#pragma unroll
        for (int i = 0; i < 4; i++) {
            int f = tid + i*256;
            int row = f >> 3, c4 = (f & 7)*4;
            *(float4*)(Ph + row*36 + c4) = *(const float4*)(Egh + row*MM + kbase + c4);
            *(float4*)(Pl + row*36 + c4) = *(const float4*)(Egl + row*MM + kbase + c4);
        }
#pragma unroll
        for (int i = 0; i < 4; i++) {
            int f = tid + i*256;
            int kr = f >> 5, c4 = (f & 31)*4;
            float4 vv = *(const float4*)(Vg + (kbase + kr)*DD + nb*128 + c4);
            float* vh = Vh + kr*136 + c4; float* vl = Vl + kr*136 + c4;
            sts_split(vv.x, vh+0, vl+0); sts_split(vv.y, vh+1, vl+1);
            sts_split(vv.z, vh+2, vl+2); sts_split(vv.w, vh+3, vl+3);
        }
        __syncthreads();
#pragma unroll
        for (int kk8 = 0; kk8 < 4; kk8++) {
            int kk = kk8*8;
            uint32_t ah[4][4], al[4][4];
#pragma unroll
            for (int mt = 0; mt < 4; mt++) {
                const float* p = Ph + (wm*64 + mt*16 + lr)*36 + kk + lc;
                ah[mt][0] = __float_as_uint(p[0]);
                ah[mt][1] = __float_as_uint(p[8*36]);
                ah[mt][2] = __float_as_uint(p[4]);
                ah[mt][3] = __float_as_uint(p[8*36+4]);
                const float* q = Pl + (wm*64 + mt*16 + lr)*36 + kk + lc;
                al[mt][0] = __float_as_uint(q[0]);
                al[mt][1] = __float_as_uint(q[8*36]);
                al[mt][2] = __float_as_uint(q[4]);
                al[mt][3] = __float_as_uint(q[8*36+4]);
            }
#pragma unroll
            for (int nt = 0; nt < 4; nt++) {
                const float* p = Vh + (kk + lc)*136 + wn*32 + nt*8 + lr;
                uint32_t bh0 = __float_as_uint(p[0]);
                uint32_t bh1 = __float_as_uint(p[4*136]);
                const float* q = Vl + (kk + lc)*136 + wn*32 + nt*8 + lr;
                uint32_t bl0 = __float_as_uint(q[0]);
                uint32_t bl1 = __float_as_uint(q[4*136]);
#pragma unroll
                for (int mt = 0; mt < 4; mt++) {
                    mma8(acc[mt][nt], ah[mt], bh0, bh1);
                    mma8(acc[mt][nt], ah[mt], bl0, bl1);
                    mma8(acc[mt][nt], al[mt], bh0, bh1);
                }
            }
        }
    }

    float* Og = g_O + b*NQ*DD + nb*128;
#pragma unroll
    for (int mt = 0; mt < 4; mt++) {
#pragma unroll
        for (int nt = 0; nt < 4; nt++) {
            int row = wm*64 + mt*16 + lr;
            int col = wn*32 + nt*8 + lc*2;
            float4 d = acc[mt][nt];
            atomicAdd(Og + row*DD + col,       d.x);
            atomicAdd(Og + row*DD + col + 1,   d.y);
            atomicAdd(Og + (row+8)*DD + col,   d.z);
            atomicAdd(Og + (row+8)*DD + col+1, d.w);
        }
    }
}

// ---------------------------------------------------------------------------
// Kernel 5: normalize by rowsum + scatter to output [B,X,H,W,C], float4.
// out[b,xo,ho,wo,co] = O[b, n=xo*4+((wo>>3)&3), cc=((wo&7)*4+(co>>3))*8+(co&7)]
// ---------------------------------------------------------------------------
__global__ __launch_bounds__(256) void k_out(float* __restrict__ out) {
    int t4 = blockIdx.x*256 + threadIdx.x;      // [0, 1M): handles 4 elems
    int t  = t4 * 4;
    int co = t & 31;                            // 4-aligned
    int wo = (t >> 5) & 127;
    int xo = (t >> 15) & 31;
    int b  = t >> 20;
    int n  = xo*4 + ((wo >> 3) & 3);
    int cc = ((wo & 7)*4 + (co >> 3))*8 + (co & 7);   // 4 consecutive
    float inv = __fdividef(1.f, g_rowsum[b*128 + n]);
    float4 v = *(const float4*)(g_O + (b*NQ + n)*DD + cc);
    v.x *= inv; v.y *= inv; v.z *= inv; v.w *= inv;
    *(float4*)(out + t) = v;
}

// ---------------------------------------------------------------------------
extern "C" void kernel_launch(void* const* d_in, const int* in_sizes, int n_in,
                              void* d_out, int out_size) {
    const float* storage = (const float*)d_in[0];
    const float* target  = (const float*)d_in[1];
    const float* w_cross = (const float*)d_in[2];
    const float* b_cross = (const float*)d_in[3];
    const float* w_q     = (const float*)d_in[4];
    const float* b_q     = (const float*)d_in[5];
    float* out = (float*)d_out;

    cudaFuncSetAttribute(k_conv,  cudaFuncAttributeMaxDynamicSharedMemorySize,
                         CONV_SMEM_FLOATS * 4);
    cudaFuncSetAttribute(k_gemm1, cudaFuncAttributeMaxDynamicSharedMemorySize,
                         G1_SMEM_FLOATS * 4);
    cudaFuncSetAttribute(k_gemm2, cudaFuncAttributeMaxDynamicSharedMemorySize,
                         G2_SMEM_FLOATS * 4);

    k_q    <<<512,  256>>>(target, w_q, b_q, w_cross);
    k_conv <<<1024, 256, CONV_SMEM_FLOATS*4>>>(storage, b_cross);
    k_gemm1<<<128,  256, G1_SMEM_FLOATS*4>>>();
    k_gemm2<<<128,  256, G2_SMEM_FLOATS*4>>>();
    k_out  <<<4096, 256>>>(out);
}